// round 16
// baseline (speedup 1.0000x reference)
#include <cuda_runtime.h>
#include <cuda_fp16.h>
#include <cstdint>
#include <math.h>

#define NB 4
#define NC 512
#define NL 2048
#define NCI 512
#define NH 8
#define ND 64

__device__ __align__(256) __half d_projh[3 * NB * NCI * NL]; // [which][b][ci][l]; theta pre-scaled 0.125*log2e
__device__ __align__(256) __half d_yh[NB * NL * NCI];        // [b][l][ci] f16 (attention out)
__device__ __align__(256) __half d_wh[4 * 512 * 512];        // [m][co][k] f16 weights
__device__ __align__(256) __half d_xh[NB * NL * 512];        // [b][l][ci] f16
__device__ __align__(256) float d_wy[NB * NC * NL];
__device__ float d_bnsum[NC];
__device__ float d_bnsq[NC];
__device__ float d_bnscale[NC];
__device__ float d_bnshift[NC];

// ---------------- helpers ----------------
__device__ __forceinline__ uint32_t fu(float x) { return __float_as_uint(x); }

__device__ __forceinline__ void hmma(float* c,
                                     uint32_t a0, uint32_t a1, uint32_t a2, uint32_t a3,
                                     uint32_t b0, uint32_t b1) {
    asm("mma.sync.aligned.m16n8k16.row.col.f32.f16.f16.f32 "
        "{%0,%1,%2,%3},{%4,%5,%6,%7},{%8,%9},{%0,%1,%2,%3};"
        : "+f"(c[0]), "+f"(c[1]), "+f"(c[2]), "+f"(c[3])
        : "r"(a0), "r"(a1), "r"(a2), "r"(a3), "r"(b0), "r"(b1));
}
__device__ __forceinline__ void ldsm4(uint32_t& r0, uint32_t& r1, uint32_t& r2, uint32_t& r3,
                                      uint32_t addr) {
    asm volatile("ldmatrix.sync.aligned.m8n8.x4.shared.b16 {%0,%1,%2,%3}, [%4];"
                 : "=r"(r0), "=r"(r1), "=r"(r2), "=r"(r3) : "r"(addr));
}
__device__ __forceinline__ void ldsm4t(uint32_t& r0, uint32_t& r1, uint32_t& r2, uint32_t& r3,
                                       uint32_t addr) {
    asm volatile("ldmatrix.sync.aligned.m8n8.x4.trans.shared.b16 {%0,%1,%2,%3}, [%4];"
                 : "=r"(r0), "=r"(r1), "=r"(r2), "=r"(r3) : "r"(addr));
}
__device__ __forceinline__ uint32_t f2h2(float a, float b) {
    __half2 h = __floats2half2_rn(a, b);
    return *reinterpret_cast<uint32_t*>(&h);
}
// packed half2 exp2: one MUFU op for two elements
__device__ __forceinline__ uint32_t h2ex2(uint32_t x) {
    uint32_t y;
    asm("ex2.approx.f16x2 %0, %1;" : "=r"(y) : "r"(x));
    return y;
}

__device__ __forceinline__ uint32_t smem_u32(const void* p) {
    uint32_t a;
    asm("{ .reg .u64 t; cvta.to.shared.u64 t, %1; cvt.u32.u64 %0, t; }" : "=r"(a) : "l"(p));
    return a;
}
__device__ __forceinline__ void cpa16(uint32_t dst, const void* src) {
    asm volatile("cp.async.ca.shared.global [%0], [%1], 16;" :: "r"(dst), "l"(src));
}
#define CP_COMMIT() asm volatile("cp.async.commit_group;" ::: "memory")
#define CP_WAIT2()  asm volatile("cp.async.wait_group 2;" ::: "memory")
#define CP_WAIT1()  asm volatile("cp.async.wait_group 1;" ::: "memory")
#define CP_WAIT0()  asm volatile("cp.async.wait_group 0;" ::: "memory")

// ---------------------------------------------------------------------------
// prep_all: x transpose fp32->f16 AND weight conversion AND BN acc zeroing.
// grid (32 lt, 8 cit, 4 b) = 1024 blocks x 256 thr.
// ---------------------------------------------------------------------------
__global__ void __launch_bounds__(256) prep_all(
    const float* __restrict__ x,
    const float* __restrict__ gw, const float* __restrict__ tw,
    const float* __restrict__ pw, const float* __restrict__ ww)
{
    __shared__ float sm[64][65];
    const int tid = threadIdx.x;
    const int bid = (blockIdx.z * gridDim.y + blockIdx.y) * gridDim.x + blockIdx.x;

    // ---- weights: one float4 per thread
    {
        int gid = bid * 256 + tid;
        if (gid < NC) { d_bnsum[gid] = 0.f; d_bnsq[gid] = 0.f; }
        int m = gid >> 16;
        int rem = gid & 65535;
        const float* src = (m == 0) ? gw : (m == 1) ? tw : (m == 2) ? pw : ww;
        float4 v = *(const float4*)(src + (size_t)rem * 4);
        uint2 o = make_uint2(f2h2(v.x, v.y), f2h2(v.z, v.w));
        *(uint2*)(d_wh + (size_t)m * 262144 + (size_t)rem * 4) = o;
    }

    // ---- x transpose [b][512 ci][2048 l] -> [b][l][ci] f16
    const int l0 = blockIdx.x * 64, ci0 = blockIdx.y * 64, b = blockIdx.z;
    const float* src = x + (size_t)b * 512 * NL;
    __half* dst = d_xh + (size_t)b * NL * 512;
#pragma unroll
    for (int it = 0; it < 4; it++) {
        int ci = (tid >> 4) + 16 * it;
        int ll = (tid & 15) * 4;
        float4 v = *(const float4*)(src + (size_t)(ci0 + ci) * NL + l0 + ll);
        sm[ci][ll] = v.x; sm[ci][ll + 1] = v.y; sm[ci][ll + 2] = v.z; sm[ci][ll + 3] = v.w;
    }
    __syncthreads();
#pragma unroll
    for (int it = 0; it < 4; it++) {
        int ll = (tid >> 4) + 16 * it;
        int cb = (tid & 15) * 4;
        uint2 o = make_uint2(f2h2(sm[cb][ll], sm[cb + 1][ll]),
                             f2h2(sm[cb + 2][ll], sm[cb + 3][ll]));
        *(uint2*)(dst + (size_t)(l0 + ll) * 512 + ci0 + cb) = o;
    }
}

// ---------------------------------------------------------------------------
// Dense GEMM f16 v4: CTA 128co x 256l, 512 threads / 16 warps (4 wm x 4 wn),
// warp tile 32co x 64l. 4-stage cp.async ring (k=64 slabs, 48KB/stage, 192KB),
// single barrier per slab (leading sync covers data-ready AND readers-done).
// STATS: fused per-channel sum / sum-sq atomics (gemm2 only)
// ---------------------------------------------------------------------------
#define DS_SMEM 196608

__device__ __forceinline__ uint32_t dswz(uint32_t base, int row, int c) {
    return base + row * 128 + ((c ^ (row & 7)) << 4);
}

template <bool HALF_OUT, bool STATS>
__device__ __forceinline__ void gemm_body_f16(
    const __half* __restrict__ Wp,    // offset to co0; row pitch 512
    const __half* __restrict__ Xp,    // [l][512]
    const float* __restrict__ bias,   // offset to co0
    float* __restrict__ outf,
    __half* __restrict__ outh,
    float* __restrict__ bnsum,        // offset to co0 (STATS only)
    float* __restrict__ bnsq,
    float oscale,
    int l0)                           // 256-wide l tile
{
    extern __shared__ float ds[];
    const uint32_t sb = smem_u32(ds);
    const int tid = threadIdx.x, lane = tid & 31, w = tid >> 5;   // w 0..15
    const int wm = w >> 2, wn = w & 3;
    const int lt = lane >> 3, li = lane & 7;
    const int srowA = tid >> 2, scpA = tid & 3;    // A: 128 rows, 2 chunks/thread
    const int srowB = tid >> 1, scpB = tid & 1;    // B: 256 rows, 4 chunks/thread

    float acc[2][8][4];
#pragma unroll
    for (int i = 0; i < 2; i++)
#pragma unroll
        for (int j = 0; j < 8; j++)
#pragma unroll
            for (int k = 0; k < 4; k++) acc[i][j][k] = 0.f;

#define DISSUE(kt) do { \
    uint32_t bA = sb + ((kt) & 3) * 49152, bB = bA + 16384; \
    const __half* wsrc = Wp + (size_t)srowA * 512 + (kt) * 64; \
    const __half* xsrc = Xp + (size_t)(l0 + srowB) * 512 + (kt) * 64; \
    _Pragma("unroll") \
    for (int u = 0; u < 2; u++) { \
        int c = scpA * 2 + u; \
        cpa16(dswz(bA, srowA, c), wsrc + c * 8); \
    } \
    _Pragma("unroll") \
    for (int u = 0; u < 4; u++) { \
        int c = scpB * 4 + u; \
        cpa16(dswz(bB, srowB, c), xsrc + c * 8); \
    } \
    CP_COMMIT(); \
} while (0)

    DISSUE(0); DISSUE(1); DISSUE(2);

    for (int kt = 0; kt < 8; kt++) {
        if (kt < 6) CP_WAIT2(); else if (kt == 6) CP_WAIT1(); else CP_WAIT0();
        __syncthreads();          // data(kt) visible + readers of buffer (kt+3)&3 done
        if (kt + 3 < 8) DISSUE(kt + 3);

        const uint32_t bA = sb + (kt & 3) * 49152, bB = bA + 16384;
#pragma unroll
        for (int kc = 0; kc < 4; kc++) {
            uint32_t af[2][4];
#pragma unroll
            for (int im = 0; im < 2; im++) {
                int row = wm * 32 + im * 16 + 8 * (lt & 1) + li;
                int c = 2 * kc + (lt >> 1);
                ldsm4(af[im][0], af[im][1], af[im][2], af[im][3], dswz(bA, row, c));
            }
#pragma unroll
            for (int bt = 0; bt < 4; bt++) {
                uint32_t b0, b1, b2, b3;
                int lrow = wn * 64 + bt * 16 + 8 * (lt >> 1) + li;
                int c = 2 * kc + (lt & 1);
                ldsm4(b0, b1, b2, b3, dswz(bB, lrow, c));
#pragma unroll
                for (int im = 0; im < 2; im++) {
                    hmma(acc[im][2 * bt],     af[im][0], af[im][1], af[im][2], af[im][3], b0, b1);
                    hmma(acc[im][2 * bt + 1], af[im][0], af[im][1], af[im][2], af[im][3], b2, b3);
                }
            }
        }
    }
#undef DISSUE

    const int r = lane >> 2, j = lane & 3;
#pragma unroll
    for (int im = 0; im < 2; im++) {
        int row = wm * 32 + im * 16 + r;
        float b0 = bias[row], b1 = bias[row + 8];
        float s0 = 0.f, q0 = 0.f, s1 = 0.f, q1 = 0.f;
#pragma unroll
        for (int nt = 0; nt < 8; nt++) {
            int col = l0 + wn * 64 + nt * 8 + 2 * j;
            float v00 = acc[im][nt][0] + b0, v01 = acc[im][nt][1] + b0;
            float v10 = acc[im][nt][2] + b1, v11 = acc[im][nt][3] + b1;
            if (HALF_OUT) {
                *(__half2*)&outh[(size_t)row * NL + col] =
                    __floats2half2_rn(v00 * oscale, v01 * oscale);
                *(__half2*)&outh[(size_t)(row + 8) * NL + col] =
                    __floats2half2_rn(v10 * oscale, v11 * oscale);
            } else {
                *(float2*)&outf[(size_t)row * NL + col] = make_float2(v00, v01);
                *(float2*)&outf[(size_t)(row + 8) * NL + col] = make_float2(v10, v11);
            }
            if (STATS) {
                s0 += v00 + v01; q0 = fmaf(v00, v00, fmaf(v01, v01, q0));
                s1 += v10 + v11; q1 = fmaf(v10, v10, fmaf(v11, v11, q1));
            }
        }
        if (STATS) {
            s0 += __shfl_xor_sync(0xffffffffu, s0, 1);
            s0 += __shfl_xor_sync(0xffffffffu, s0, 2);
            q0 += __shfl_xor_sync(0xffffffffu, q0, 1);
            q0 += __shfl_xor_sync(0xffffffffu, q0, 2);
            s1 += __shfl_xor_sync(0xffffffffu, s1, 1);
            s1 += __shfl_xor_sync(0xffffffffu, s1, 2);
            q1 += __shfl_xor_sync(0xffffffffu, q1, 1);
            q1 += __shfl_xor_sync(0xffffffffu, q1, 2);
            if (j == 0) {
                atomicAdd(&bnsum[row], s0);
                atomicAdd(&bnsq[row], q0);
                atomicAdd(&bnsum[row + 8], s1);
                atomicAdd(&bnsq[row + 8], q1);
            }
        }
    }
}

__global__ void __launch_bounds__(512, 1) proj_tc(
    const float* __restrict__ gb, const float* __restrict__ tbb, const float* __restrict__ pb)
{
    const int which = blockIdx.y >> 2;
    const int co0 = (blockIdx.y & 3) * 128;
    const int b = blockIdx.z;
    const float* bias = (which == 0 ? gb : which == 1 ? tbb : pb);
    // theta gets 0.125 * log2(e) so attention can use ex2 directly
    gemm_body_f16<true, false>(d_wh + ((size_t)which * 512 + co0) * 512,
                               d_xh + (size_t)b * NL * 512,
                               bias + co0,
                               nullptr,
                               d_projh + ((size_t)which * NB + b) * NCI * NL + (size_t)co0 * NL,
                               nullptr, nullptr,
                               which == 1 ? 0.18033688f : 1.0f,
                               blockIdx.x * 256);
}

__global__ void __launch_bounds__(512, 1) gemm2_tc(const float* __restrict__ wb)
{
    const int co0 = blockIdx.y * 128;
    const int b = blockIdx.z;
    gemm_body_f16<false, true>(d_wh + ((size_t)3 * 512 + co0) * 512,
                               d_yh + (size_t)b * NL * 512,
                               wb + co0,
                               d_wy + (size_t)b * NC * NL + (size_t)co0 * NL,
                               nullptr,
                               d_bnsum + co0, d_bnsq + co0,
                               1.0f, blockIdx.x * 256);
}

// ---------------------------------------------------------------------------
// Attention (round-12, unchanged): 4 warps x 32q, f16 m16n8k16, cp.async,
// hoisted Q frags, f16x2 ex2, row sums via ones-HMMA.
// ---------------------------------------------------------------------------
#define AT_SMEM 49152

__device__ __forceinline__ uint32_t qswz(uint32_t base, int d, int qblk) {
    return base + d * 256 + ((qblk ^ (d & 7)) << 4);
}
__device__ __forceinline__ uint32_t kswz(uint32_t base, int d, int cblk) {
    return base + d * 128 + ((cblk ^ (d & 7)) << 4);
}

__global__ void __launch_bounds__(128, 2) attn_tc()
{
    extern __shared__ char smc[];
    const uint32_t sb = smem_u32(smc);
    const uint32_t Qb = sb, Kb = sb + 16384, Vb = sb + 32768;

    const int tid = threadIdx.x, lane = tid & 31, w = tid >> 5;   // w in 0..3
    const int r = lane >> 2, j = lane & 3;
    const int lt = lane >> 3, li = lane & 7;
    const int q0 = blockIdx.x * 128;
    const int b = blockIdx.y >> 3, h = blockIdx.y & 7;

    const __half* thetah = d_projh + ((size_t)(1 * NB + b) * NCI + h * ND) * NL;
    const __half* phih   = d_projh + ((size_t)(2 * NB + b) * NCI + h * ND) * NL;
    const __half* gxh    = d_projh + ((size_t)(0 * NB + b) * NCI + h * ND) * NL;

    const int srow = tid >> 1;      // staging d row (0..63)
    const int shalf = tid & 1;

#pragma unroll
    for (int u = 0; u < 8; u++) {
        int ch = shalf * 8 + u;
        cpa16(qswz(Qb, srow, ch), thetah + (size_t)srow * NL + q0 + ch * 8);
    }
#pragma unroll
    for (int u = 0; u < 4; u++) {
        int ch = shalf * 4 + u;
        cpa16(kswz(Kb, srow, ch), phih + (size_t)srow * NL + ch * 8);
        cpa16(kswz(Vb, srow, ch), gxh + (size_t)srow * NL + ch * 8);
    }
    CP_COMMIT();

    const uint32_t ONES = 0x3C003C00u;
    uint32_t qf[2][4][4];
    float acc_o[2][8][4];
    float acc_l[2][4];
#pragma unroll
    for (int m = 0; m < 2; m++) {
#pragma unroll
        for (int n = 0; n < 8; n++)
#pragma unroll
            for (int k = 0; k < 4; k++) acc_o[m][n][k] = 0.f;
#pragma unroll
        for (int k = 0; k < 4; k++) acc_l[m][k] = 0.f;
    }

    for (int it = 0; it < 32; it++) {
        __syncthreads();
        if (it + 1 < 32) {
            const int nb_ = (it + 1) & 1;
            const size_t kko = (size_t)(it + 1) * 64;
#pragma unroll
            for (int u = 0; u < 4; u++) {
                int ch = shalf * 4 + u;
                cpa16(kswz(Kb + nb_ * 8192, srow, ch), phih + (size_t)srow * NL + kko + ch * 8);
                cpa16(kswz(Vb + nb_ * 8192, srow, ch), gxh + (size_t)srow * NL + kko + ch * 8);
            }
            CP_COMMIT();
            CP_WAIT1();
        } else {
            CP_WAIT0();
        }
        __syncthreads();

        if (it == 0) {
#pragma unroll
            for (int m = 0; m < 2; m++)
#pragma unroll
                for (int s = 0; s < 4; s++) {
                    int d = 16 * s + 8 * (lt >> 1) + li;
                    int qblk = 4 * w + 2 * m + (lt & 1);
                    ldsm4t(qf[m][s][0], qf[m][s][1], qf[m][s][2], qf[m][s][3], qswz(Qb, d, qblk));
                }
        }

        const uint32_t Kc = Kb + (it & 1) * 8192;
        const uint32_t Vc = Vb + (it & 1) * 8192;

        float s_acc[2][8][4];
#pragma unroll
        for (int m = 0; m < 2; m++)
#pragma unroll
            for (int n = 0; n < 8; n++)
#pragma unroll
                for (int k = 0; k < 4; k++) s_acc[m][n][k] = 0.f;

#pragma unroll
        for (int s = 0; s < 4; s++) {
#pragma unroll
            for (int np = 0; np < 4; np++) {
                uint32_t k0, k1, k2, k3;
                int d = 16 * s + 8 * (lt & 1) + li;
                int cb = 2 * np + (lt >> 1);
                ldsm4t(k0, k1, k2, k3, kswz(Kc, d, cb));
#pragma unroll
                for (int m = 0; m < 2; m++) {
                    hmma(s_acc[m][2 * np],     qf[m][s][0], qf[m][s][1], qf[m][s][2], qf[m][s][3], k0, k1);
                    hmma(s_acc[m][2 * np + 1], qf[m][s][0], qf[m][s][1], qf[m][s][2], qf[m][s][3], k2, k3);
                }
            }
        }

#pragma unroll
        for (int sv = 0; sv < 4; sv++) {
            uint32_t pa[2][4];
#pragma unroll
            for (int m = 0; m < 2; m++) {
                pa[m][0] = h2ex2(f2h2(s_acc[m][2 * sv][0],     s_acc[m][2 * sv][1]));
                pa[m][1] = h2ex2(f2h2(s_acc[m][2 * sv][2],     s_acc[m][2 * sv][3]));
                pa[m][2] = h2ex2(f2h2(s_acc[m][2 * sv + 1][0], s_acc[m][2 * sv + 1][1]));
                pa[m][3] = h2ex2(f2h2(s_acc[m][2 * sv + 1][2], s_acc[m][2 * sv + 1][3]));
                hmma(acc_l[m], pa[m][0], pa[m][1], pa[m][2], pa[m][3], ONES, ONES);
            }
#pragma unroll
            for (int dp = 0; dp < 4; dp++) {
                uint32_t v0, v1, v2, v3;
                int d = 16 * dp + 8 * (lt >> 1) + li;
                int cb = 2 * sv + (lt & 1);
                ldsm4(v0, v1, v2, v3, kswz(Vc, d, cb));
#pragma unroll
                for (int m = 0; m < 2; m++) {
                    hmma(acc_o[m][2 * dp],     pa[m][0], pa[m][1], pa[m][2], pa[m][3], v0, v1);
                    hmma(acc_o[m][2 * dp + 1], pa[m][0], pa[m][1], pa[m][2], pa[m][3], v2, v3);
                }
            }
        }
    }

#pragma unroll
    for (int m = 0; m < 2; m++) {
        const float inv0 = 1.0f / acc_l[m][0];
        const float inv1 = 1.0f / acc_l[m][2];
        const int q = 32 * w + 16 * m + r;
        __half* y0 = d_yh + ((size_t)b * NL + q0 + q) * 512 + h * 64;
        __half* y1 = y0 + (size_t)8 * 512;
#pragma unroll
        for (int nd = 0; nd < 8; nd++) {
            int d = 8 * nd + 2 * j;
            *(__half2*)(y0 + d) = __floats2half2_rn(acc_o[m][nd][0] * inv0, acc_o[m][nd][1] * inv0);
            *(__half2*)(y1 + d) = __floats2half2_rn(acc_o[m][nd][2] * inv1, acc_o[m][nd][3] * inv1);
        }
    }
}

// ---------------------------------------------------------------------------
// BatchNorm: finalize -> per-channel scale/shift; apply = pure FMA, 2 float4/thr
// ---------------------------------------------------------------------------
__global__ void __launch_bounds__(256) bn_finalize(
    const float* __restrict__ gamma, const float* __restrict__ beta)
{
    int c = blockIdx.x * 256 + threadIdx.x;
    float mean = d_bnsum[c] * (1.0f / (NB * NL));
    float var = d_bnsq[c] * (1.0f / (NB * NL)) - mean * mean;
    float scale = rsqrtf(var + 1e-5f) * gamma[c];
    d_bnscale[c] = scale;
    d_bnshift[c] = beta[c] - mean * scale;
}

__global__ void __launch_bounds__(256) bn_apply_kernel(float* __restrict__ out)
{
    int i8 = blockIdx.x * 256 + threadIdx.x;
    int i4 = i8 * 2;
    int c = (i4 >> 9) & (NC - 1);        // both float4s in same channel (i4 even)
    float sc = d_bnscale[c], sh = d_bnshift[c];
    float4 v0 = reinterpret_cast<const float4*>(d_wy)[i4];
    float4 v1 = reinterpret_cast<const float4*>(d_wy)[i4 + 1];
    float4 o0 = make_float4(fmaf(v0.x, sc, sh), fmaf(v0.y, sc, sh),
                            fmaf(v0.z, sc, sh), fmaf(v0.w, sc, sh));
    float4 o1 = make_float4(fmaf(v1.x, sc, sh), fmaf(v1.y, sc, sh),
                            fmaf(v1.z, sc, sh), fmaf(v1.w, sc, sh));
    reinterpret_cast<float4*>(out)[i4] = o0;
    reinterpret_cast<float4*>(out)[i4 + 1] = o1;
}

// ---------------------------------------------------------------------------
extern "C" void kernel_launch(void* const* d_in, const int* in_sizes, int n_in,
                              void* d_out, int out_size)
{
    const float* x     = (const float*)d_in[0];
    const float* gw    = (const float*)d_in[1];
    const float* gb    = (const float*)d_in[2];
    const float* tw    = (const float*)d_in[3];
    const float* tb    = (const float*)d_in[4];
    const float* pw    = (const float*)d_in[5];
    const float* pb    = (const float*)d_in[6];
    const float* ww    = (const float*)d_in[7];
    const float* wb    = (const float*)d_in[8];
    const float* gamma = (const float*)d_in[9];
    const float* beta  = (const float*)d_in[10];
    float* out = (float*)d_out;

    cudaFuncSetAttribute(proj_tc, cudaFuncAttributeMaxDynamicSharedMemorySize, DS_SMEM);
    cudaFuncSetAttribute(gemm2_tc, cudaFuncAttributeMaxDynamicSharedMemorySize, DS_SMEM);
    cudaFuncSetAttribute(attn_tc, cudaFuncAttributeMaxDynamicSharedMemorySize, AT_SMEM);

    prep_all<<<dim3(32, 8, 4), 256>>>(x, gw, tw, pw, ww);
    proj_tc<<<dim3(8, 12, 4), 512, DS_SMEM>>>(gb, tb, pb);
    attn_tc<<<dim3(16, 32), 128, AT_SMEM>>>();
    gemm2_tc<<<dim3(8, 4, 4), 512, DS_SMEM>>>(wb);
    bn_finalize<<<2, 256>>>(gamma, beta);
    bn_apply_kernel<<<(NB * NC * NL) / 2048, 256>>>(out);
}

// round 17
// speedup vs baseline: 1.0125x; 1.0125x over previous
#include <cuda_runtime.h>
#include <cuda_fp16.h>
#include <cstdint>
#include <math.h>

#define NB 4
#define NC 512
#define NL 2048
#define NCI 512
#define NH 8
#define ND 64

__device__ __align__(256) __half d_projh[3 * NB * NCI * NL]; // [which][b][ci][l]; theta pre-scaled 0.125*log2e
__device__ __align__(256) __half d_yh[NB * NL * NCI];        // [b][l][ci] f16 (attention out)
__device__ __align__(256) __half d_wh[4 * 512 * 512];        // [m][co][k] f16 weights
__device__ __align__(256) __half d_xh[NB * NL * 512];        // [b][l][ci] f16
__device__ __align__(256) float d_wy[NB * NC * NL];
__device__ float d_bnsum[NC];
__device__ float d_bnsq[NC];
__device__ float d_bnscale[NC];
__device__ float d_bnshift[NC];

// ---------------- helpers ----------------
__device__ __forceinline__ uint32_t fu(float x) { return __float_as_uint(x); }

__device__ __forceinline__ void hmma(float* c,
                                     uint32_t a0, uint32_t a1, uint32_t a2, uint32_t a3,
                                     uint32_t b0, uint32_t b1) {
    asm("mma.sync.aligned.m16n8k16.row.col.f32.f16.f16.f32 "
        "{%0,%1,%2,%3},{%4,%5,%6,%7},{%8,%9},{%0,%1,%2,%3};"
        : "+f"(c[0]), "+f"(c[1]), "+f"(c[2]), "+f"(c[3])
        : "r"(a0), "r"(a1), "r"(a2), "r"(a3), "r"(b0), "r"(b1));
}
__device__ __forceinline__ void ldsm4(uint32_t& r0, uint32_t& r1, uint32_t& r2, uint32_t& r3,
                                      uint32_t addr) {
    asm volatile("ldmatrix.sync.aligned.m8n8.x4.shared.b16 {%0,%1,%2,%3}, [%4];"
                 : "=r"(r0), "=r"(r1), "=r"(r2), "=r"(r3) : "r"(addr));
}
__device__ __forceinline__ void ldsm4t(uint32_t& r0, uint32_t& r1, uint32_t& r2, uint32_t& r3,
                                       uint32_t addr) {
    asm volatile("ldmatrix.sync.aligned.m8n8.x4.trans.shared.b16 {%0,%1,%2,%3}, [%4];"
                 : "=r"(r0), "=r"(r1), "=r"(r2), "=r"(r3) : "r"(addr));
}
__device__ __forceinline__ uint32_t f2h2(float a, float b) {
    __half2 h = __floats2half2_rn(a, b);
    return *reinterpret_cast<uint32_t*>(&h);
}
// packed half2 exp2: one MUFU op for two elements
__device__ __forceinline__ uint32_t h2ex2(uint32_t x) {
    uint32_t y;
    asm("ex2.approx.f16x2 %0, %1;" : "=r"(y) : "r"(x));
    return y;
}

__device__ __forceinline__ uint32_t smem_u32(const void* p) {
    uint32_t a;
    asm("{ .reg .u64 t; cvta.to.shared.u64 t, %1; cvt.u32.u64 %0, t; }" : "=r"(a) : "l"(p));
    return a;
}
__device__ __forceinline__ void cpa16(uint32_t dst, const void* src) {
    asm volatile("cp.async.ca.shared.global [%0], [%1], 16;" :: "r"(dst), "l"(src));
}
#define CP_COMMIT() asm volatile("cp.async.commit_group;" ::: "memory")
#define CP_WAIT2()  asm volatile("cp.async.wait_group 2;" ::: "memory")
#define CP_WAIT1()  asm volatile("cp.async.wait_group 1;" ::: "memory")
#define CP_WAIT0()  asm volatile("cp.async.wait_group 0;" ::: "memory")

// ---------------------------------------------------------------------------
// prep_all: x transpose fp32->f16 AND weight conversion AND BN acc zeroing.
// grid (32 lt, 8 cit, 4 b) = 1024 blocks x 256 thr.
// ---------------------------------------------------------------------------
__global__ void __launch_bounds__(256) prep_all(
    const float* __restrict__ x,
    const float* __restrict__ gw, const float* __restrict__ tw,
    const float* __restrict__ pw, const float* __restrict__ ww)
{
    __shared__ float sm[64][65];
    const int tid = threadIdx.x;
    const int bid = (blockIdx.z * gridDim.y + blockIdx.y) * gridDim.x + blockIdx.x;

    // ---- weights: one float4 per thread
    {
        int gid = bid * 256 + tid;
        if (gid < NC) { d_bnsum[gid] = 0.f; d_bnsq[gid] = 0.f; }
        int m = gid >> 16;
        int rem = gid & 65535;
        const float* src = (m == 0) ? gw : (m == 1) ? tw : (m == 2) ? pw : ww;
        float4 v = *(const float4*)(src + (size_t)rem * 4);
        uint2 o = make_uint2(f2h2(v.x, v.y), f2h2(v.z, v.w));
        *(uint2*)(d_wh + (size_t)m * 262144 + (size_t)rem * 4) = o;
    }

    // ---- x transpose [b][512 ci][2048 l] -> [b][l][ci] f16
    const int l0 = blockIdx.x * 64, ci0 = blockIdx.y * 64, b = blockIdx.z;
    const float* src = x + (size_t)b * 512 * NL;
    __half* dst = d_xh + (size_t)b * NL * 512;
#pragma unroll
    for (int it = 0; it < 4; it++) {
        int ci = (tid >> 4) + 16 * it;
        int ll = (tid & 15) * 4;
        float4 v = *(const float4*)(src + (size_t)(ci0 + ci) * NL + l0 + ll);
        sm[ci][ll] = v.x; sm[ci][ll + 1] = v.y; sm[ci][ll + 2] = v.z; sm[ci][ll + 3] = v.w;
    }
    __syncthreads();
#pragma unroll
    for (int it = 0; it < 4; it++) {
        int ll = (tid >> 4) + 16 * it;
        int cb = (tid & 15) * 4;
        uint2 o = make_uint2(f2h2(sm[cb][ll], sm[cb + 1][ll]),
                             f2h2(sm[cb + 2][ll], sm[cb + 3][ll]));
        *(uint2*)(dst + (size_t)(l0 + ll) * 512 + ci0 + cb) = o;
    }
}

// ---------------------------------------------------------------------------
// Dense GEMM f16 v4 (round-16): CTA 128co x 256l, 512 thr / 16 warps,
// warp tile 32x64, 4-stage cp.async ring, single barrier per slab.
// STATS: fused per-channel sum / sum-sq atomics (gemm2 only)
// ---------------------------------------------------------------------------
#define DS_SMEM 196608

__device__ __forceinline__ uint32_t dswz(uint32_t base, int row, int c) {
    return base + row * 128 + ((c ^ (row & 7)) << 4);
}

template <bool HALF_OUT, bool STATS>
__device__ __forceinline__ void gemm_body_f16(
    const __half* __restrict__ Wp,
    const __half* __restrict__ Xp,
    const float* __restrict__ bias,
    float* __restrict__ outf,
    __half* __restrict__ outh,
    float* __restrict__ bnsum,
    float* __restrict__ bnsq,
    float oscale,
    int l0)
{
    extern __shared__ float ds[];
    const uint32_t sb = smem_u32(ds);
    const int tid = threadIdx.x, lane = tid & 31, w = tid >> 5;
    const int wm = w >> 2, wn = w & 3;
    const int lt = lane >> 3, li = lane & 7;
    const int srowA = tid >> 2, scpA = tid & 3;
    const int srowB = tid >> 1, scpB = tid & 1;

    float acc[2][8][4];
#pragma unroll
    for (int i = 0; i < 2; i++)
#pragma unroll
        for (int j = 0; j < 8; j++)
#pragma unroll
            for (int k = 0; k < 4; k++) acc[i][j][k] = 0.f;

#define DISSUE(kt) do { \
    uint32_t bA = sb + ((kt) & 3) * 49152, bB = bA + 16384; \
    const __half* wsrc = Wp + (size_t)srowA * 512 + (kt) * 64; \
    const __half* xsrc = Xp + (size_t)(l0 + srowB) * 512 + (kt) * 64; \
    _Pragma("unroll") \
    for (int u = 0; u < 2; u++) { \
        int c = scpA * 2 + u; \
        cpa16(dswz(bA, srowA, c), wsrc + c * 8); \
    } \
    _Pragma("unroll") \
    for (int u = 0; u < 4; u++) { \
        int c = scpB * 4 + u; \
        cpa16(dswz(bB, srowB, c), xsrc + c * 8); \
    } \
    CP_COMMIT(); \
} while (0)

    DISSUE(0); DISSUE(1); DISSUE(2);

    for (int kt = 0; kt < 8; kt++) {
        if (kt < 6) CP_WAIT2(); else if (kt == 6) CP_WAIT1(); else CP_WAIT0();
        __syncthreads();
        if (kt + 3 < 8) DISSUE(kt + 3);

        const uint32_t bA = sb + (kt & 3) * 49152, bB = bA + 16384;
#pragma unroll
        for (int kc = 0; kc < 4; kc++) {
            uint32_t af[2][4];
#pragma unroll
            for (int im = 0; im < 2; im++) {
                int row = wm * 32 + im * 16 + 8 * (lt & 1) + li;
                int c = 2 * kc + (lt >> 1);
                ldsm4(af[im][0], af[im][1], af[im][2], af[im][3], dswz(bA, row, c));
            }
#pragma unroll
            for (int bt = 0; bt < 4; bt++) {
                uint32_t b0, b1, b2, b3;
                int lrow = wn * 64 + bt * 16 + 8 * (lt >> 1) + li;
                int c = 2 * kc + (lt & 1);
                ldsm4(b0, b1, b2, b3, dswz(bB, lrow, c));
#pragma unroll
                for (int im = 0; im < 2; im++) {
                    hmma(acc[im][2 * bt],     af[im][0], af[im][1], af[im][2], af[im][3], b0, b1);
                    hmma(acc[im][2 * bt + 1], af[im][0], af[im][1], af[im][2], af[im][3], b2, b3);
                }
            }
        }
    }
#undef DISSUE

    const int r = lane >> 2, j = lane & 3;
#pragma unroll
    for (int im = 0; im < 2; im++) {
        int row = wm * 32 + im * 16 + r;
        float b0 = bias[row], b1 = bias[row + 8];
        float s0 = 0.f, q0 = 0.f, s1 = 0.f, q1 = 0.f;
#pragma unroll
        for (int nt = 0; nt < 8; nt++) {
            int col = l0 + wn * 64 + nt * 8 + 2 * j;
            float v00 = acc[im][nt][0] + b0, v01 = acc[im][nt][1] + b0;
            float v10 = acc[im][nt][2] + b1, v11 = acc[im][nt][3] + b1;
            if (HALF_OUT) {
                *(__half2*)&outh[(size_t)row * NL + col] =
                    __floats2half2_rn(v00 * oscale, v01 * oscale);
                *(__half2*)&outh[(size_t)(row + 8) * NL + col] =
                    __floats2half2_rn(v10 * oscale, v11 * oscale);
            } else {
                *(float2*)&outf[(size_t)row * NL + col] = make_float2(v00, v01);
                *(float2*)&outf[(size_t)(row + 8) * NL + col] = make_float2(v10, v11);
            }
            if (STATS) {
                s0 += v00 + v01; q0 = fmaf(v00, v00, fmaf(v01, v01, q0));
                s1 += v10 + v11; q1 = fmaf(v10, v10, fmaf(v11, v11, q1));
            }
        }
        if (STATS) {
            s0 += __shfl_xor_sync(0xffffffffu, s0, 1);
            s0 += __shfl_xor_sync(0xffffffffu, s0, 2);
            q0 += __shfl_xor_sync(0xffffffffu, q0, 1);
            q0 += __shfl_xor_sync(0xffffffffu, q0, 2);
            s1 += __shfl_xor_sync(0xffffffffu, s1, 1);
            s1 += __shfl_xor_sync(0xffffffffu, s1, 2);
            q1 += __shfl_xor_sync(0xffffffffu, q1, 1);
            q1 += __shfl_xor_sync(0xffffffffu, q1, 2);
            if (j == 0) {
                atomicAdd(&bnsum[row], s0);
                atomicAdd(&bnsq[row], q0);
                atomicAdd(&bnsum[row + 8], s1);
                atomicAdd(&bnsq[row + 8], q1);
            }
        }
    }
}

__global__ void __launch_bounds__(512, 1) proj_tc(
    const float* __restrict__ gb, const float* __restrict__ tbb, const float* __restrict__ pb)
{
    const int which = blockIdx.y >> 2;
    const int co0 = (blockIdx.y & 3) * 128;
    const int b = blockIdx.z;
    const float* bias = (which == 0 ? gb : which == 1 ? tbb : pb);
    gemm_body_f16<true, false>(d_wh + ((size_t)which * 512 + co0) * 512,
                               d_xh + (size_t)b * NL * 512,
                               bias + co0,
                               nullptr,
                               d_projh + ((size_t)which * NB + b) * NCI * NL + (size_t)co0 * NL,
                               nullptr, nullptr,
                               which == 1 ? 0.18033688f : 1.0f,
                               blockIdx.x * 256);
}

__global__ void __launch_bounds__(512, 1) gemm2_tc(const float* __restrict__ wb)
{
    const int co0 = blockIdx.y * 128;
    const int b = blockIdx.z;
    gemm_body_f16<false, true>(d_wh + ((size_t)3 * 512 + co0) * 512,
                               d_yh + (size_t)b * NL * 512,
                               wb + co0,
                               d_wy + (size_t)b * NC * NL + (size_t)co0 * NL,
                               nullptr,
                               d_bnsum + co0, d_bnsq + co0,
                               1.0f, blockIdx.x * 256);
}

// ---------------------------------------------------------------------------
// Attention v7: 4-stage K/V cp.async ring, SINGLE barrier per k-tile.
// 4 warps x 32q, f16 m16n8k16, hoisted Q frags, f16x2 ex2, ones-HMMA row sums.
// Smem: Q 16K @0, K 4x8K @16384, V 4x8K @49152 -> 80KB, 2 CTAs/SM.
// ---------------------------------------------------------------------------
#define AT_SMEM 81920

__device__ __forceinline__ uint32_t qswz(uint32_t base, int d, int qblk) {
    return base + d * 256 + ((qblk ^ (d & 7)) << 4);
}
__device__ __forceinline__ uint32_t kswz(uint32_t base, int d, int cblk) {
    return base + d * 128 + ((cblk ^ (d & 7)) << 4);
}

__global__ void __launch_bounds__(128, 2) attn_tc()
{
    extern __shared__ char smc[];
    const uint32_t sb = smem_u32(smc);
    const uint32_t Qb = sb, Kb = sb + 16384, Vb = sb + 49152;

    const int tid = threadIdx.x, lane = tid & 31, w = tid >> 5;   // w in 0..3
    const int r = lane >> 2, j = lane & 3;
    const int lt = lane >> 3, li = lane & 7;
    const int q0 = blockIdx.x * 128;
    const int b = blockIdx.y >> 3, h = blockIdx.y & 7;

    const __half* thetah = d_projh + ((size_t)(1 * NB + b) * NCI + h * ND) * NL;
    const __half* phih   = d_projh + ((size_t)(2 * NB + b) * NCI + h * ND) * NL;
    const __half* gxh    = d_projh + ((size_t)(0 * NB + b) * NCI + h * ND) * NL;

    const int srow = tid >> 1;      // staging d row (0..63)
    const int shalf = tid & 1;

#define AISSUE(it) do { \
    const uint32_t Kd = Kb + ((it) & 3) * 8192; \
    const uint32_t Vd = Vb + ((it) & 3) * 8192; \
    const size_t kko = (size_t)(it) * 64; \
    _Pragma("unroll") \
    for (int u = 0; u < 4; u++) { \
        int ch = shalf * 4 + u; \
        cpa16(kswz(Kd, srow, ch), phih + (size_t)srow * NL + kko + ch * 8); \
        cpa16(kswz(Vd, srow, ch), gxh + (size_t)srow * NL + kko + ch * 8); \
    } \
    CP_COMMIT(); \
} while (0)

    // ---- prologue: group 0 = Q + KV tile 0; groups 1,2 = KV tiles 1,2
#pragma unroll
    for (int u = 0; u < 8; u++) {
        int ch = shalf * 8 + u;
        cpa16(qswz(Qb, srow, ch), thetah + (size_t)srow * NL + q0 + ch * 8);
    }
    AISSUE(0);
    AISSUE(1);
    AISSUE(2);

    const uint32_t ONES = 0x3C003C00u;
    uint32_t qf[2][4][4];
    float acc_o[2][8][4];
    float acc_l[2][4];
#pragma unroll
    for (int m = 0; m < 2; m++) {
#pragma unroll
        for (int n = 0; n < 8; n++)
#pragma unroll
            for (int k = 0; k < 4; k++) acc_o[m][n][k] = 0.f;
#pragma unroll
        for (int k = 0; k < 4; k++) acc_l[m][k] = 0.f;
    }

    for (int it = 0; it < 32; it++) {
        if (it < 30) CP_WAIT2(); else if (it == 30) CP_WAIT1(); else CP_WAIT0();
        __syncthreads();   // data(it) visible + readers of buf (it+3)&3 (iter it-1) done
        if (it + 3 < 32) AISSUE(it + 3);

        if (it == 0) {
#pragma unroll
            for (int m = 0; m < 2; m++)
#pragma unroll
                for (int s = 0; s < 4; s++) {
                    int d = 16 * s + 8 * (lt >> 1) + li;
                    int qblk = 4 * w + 2 * m + (lt & 1);
                    ldsm4t(qf[m][s][0], qf[m][s][1], qf[m][s][2], qf[m][s][3], qswz(Qb, d, qblk));
                }
        }

        const uint32_t Kc = Kb + (it & 3) * 8192;
        const uint32_t Vc = Vb + (it & 3) * 8192;

        float s_acc[2][8][4];
#pragma unroll
        for (int m = 0; m < 2; m++)
#pragma unroll
            for (int n = 0; n < 8; n++)
#pragma unroll
                for (int k = 0; k < 4; k++) s_acc[m][n][k] = 0.f;

#pragma unroll
        for (int s = 0; s < 4; s++) {
#pragma unroll
            for (int np = 0; np < 4; np++) {
                uint32_t k0, k1, k2, k3;
                int d = 16 * s + 8 * (lt & 1) + li;
                int cb = 2 * np + (lt >> 1);
                ldsm4t(k0, k1, k2, k3, kswz(Kc, d, cb));
#pragma unroll
                for (int m = 0; m < 2; m++) {
                    hmma(s_acc[m][2 * np],     qf[m][s][0], qf[m][s][1], qf[m][s][2], qf[m][s][3], k0, k1);
                    hmma(s_acc[m][2 * np + 1], qf[m][s][0], qf[m][s][1], qf[m][s][2], qf[m][s][3], k2, k3);
                }
            }
        }

#pragma unroll
        for (int sv = 0; sv < 4; sv++) {
            uint32_t pa[2][4];
#pragma unroll
            for (int m = 0; m < 2; m++) {
                pa[m][0] = h2ex2(f2h2(s_acc[m][2 * sv][0],     s_acc[m][2 * sv][1]));
                pa[m][1] = h2ex2(f2h2(s_acc[m][2 * sv][2],     s_acc[m][2 * sv][3]));
                pa[m][2] = h2ex2(f2h2(s_acc[m][2 * sv + 1][0], s_acc[m][2 * sv + 1][1]));
                pa[m][3] = h2ex2(f2h2(s_acc[m][2 * sv + 1][2], s_acc[m][2 * sv + 1][3]));
                hmma(acc_l[m], pa[m][0], pa[m][1], pa[m][2], pa[m][3], ONES, ONES);
            }
#pragma unroll
            for (int dp = 0; dp < 4; dp++) {
                uint32_t v0, v1, v2, v3;
                int d = 16 * dp + 8 * (lt >> 1) + li;
                int cb = 2 * sv + (lt & 1);
                ldsm4(v0, v1, v2, v3, kswz(Vc, d, cb));
#pragma unroll
                for (int m = 0; m < 2; m++) {
                    hmma(acc_o[m][2 * dp],     pa[m][0], pa[m][1], pa[m][2], pa[m][3], v0, v1);
                    hmma(acc_o[m][2 * dp + 1], pa[m][0], pa[m][1], pa[m][2], pa[m][3], v2, v3);
                }
            }
        }
    }
#undef AISSUE

#pragma unroll
    for (int m = 0; m < 2; m++) {
        const float inv0 = 1.0f / acc_l[m][0];
        const float inv1 = 1.0f / acc_l[m][2];
        const int q = 32 * w + 16 * m + r;
        __half* y0 = d_yh + ((size_t)b * NL + q0 + q) * 512 + h * 64;
        __half* y1 = y0 + (size_t)8 * 512;
#pragma unroll
        for (int nd = 0; nd < 8; nd++) {
            int d = 8 * nd + 2 * j;
            *(__half2*)(y0 + d) = __floats2half2_rn(acc_o[m][nd][0] * inv0, acc_o[m][nd][1] * inv0);
            *(__half2*)(y1 + d) = __floats2half2_rn(acc_o[m][nd][2] * inv1, acc_o[m][nd][3] * inv1);
        }
    }
}

// ---------------------------------------------------------------------------
// BatchNorm: finalize -> per-channel scale/shift; apply = pure FMA, 2 float4/thr
// ---------------------------------------------------------------------------
__global__ void __launch_bounds__(256) bn_finalize(
    const float* __restrict__ gamma, const float* __restrict__ beta)
{
    int c = blockIdx.x * 256 + threadIdx.x;
    float mean = d_bnsum[c] * (1.0f / (NB * NL));
    float var = d_bnsq[c] * (1.0f / (NB * NL)) - mean * mean;
    float scale = rsqrtf(var + 1e-5f) * gamma[c];
    d_bnscale[c] = scale;
    d_bnshift[c] = beta[c] - mean * scale;
}

__global__ void __launch_bounds__(256) bn_apply_kernel(float* __restrict__ out)
{
    int i8 = blockIdx.x * 256 + threadIdx.x;
    int i4 = i8 * 2;
    int c = (i4 >> 9) & (NC - 1);
    float sc = d_bnscale[c], sh = d_bnshift[c];
    float4 v0 = reinterpret_cast<const float4*>(d_wy)[i4];
    float4 v1 = reinterpret_cast<const float4*>(d_wy)[i4 + 1];
    float4 o0 = make_float4(fmaf(v0.x, sc, sh), fmaf(v0.y, sc, sh),
                            fmaf(v0.z, sc, sh), fmaf(v0.w, sc, sh));
    float4 o1 = make_float4(fmaf(v1.x, sc, sh), fmaf(v1.y, sc, sh),
                            fmaf(v1.z, sc, sh), fmaf(v1.w, sc, sh));
    reinterpret_cast<float4*>(out)[i4] = o0;
    reinterpret_cast<float4*>(out)[i4 + 1] = o1;
}

// ---------------------------------------------------------------------------
extern "C" void kernel_launch(void* const* d_in, const int* in_sizes, int n_in,
                              void* d_out, int out_size)
{
    const float* x     = (const float*)d_in[0];
    const float* gw    = (const float*)d_in[1];
    const float* gb    = (const float*)d_in[2];
    const float* tw    = (const float*)d_in[3];
    const float* tb    = (const float*)d_in[4];
    const float* pw    = (const float*)d_in[5];
    const float* pb    = (const float*)d_in[6];
    const float* ww    = (const float*)d_in[7];
    const float* wb    = (const float*)d_in[8];
    const float* gamma = (const float*)d_in[9];
    const float* beta  = (const float*)d_in[10];
    float* out = (float*)d_out;

    cudaFuncSetAttribute(proj_tc, cudaFuncAttributeMaxDynamicSharedMemorySize, DS_SMEM);
    cudaFuncSetAttribute(gemm2_tc, cudaFuncAttributeMaxDynamicSharedMemorySize, DS_SMEM);
    cudaFuncSetAttribute(attn_tc, cudaFuncAttributeMaxDynamicSharedMemorySize, AT_SMEM);

    prep_all<<<dim3(32, 8, 4), 256>>>(x, gw, tw, pw, ww);
    proj_tc<<<dim3(8, 12, 4), 512, DS_SMEM>>>(gb, tb, pb);
    attn_tc<<<dim3(16, 32), 128, AT_SMEM>>>();
    gemm2_tc<<<dim3(8, 4, 4), 512, DS_SMEM>>>(wb);
    bn_finalize<<<2, 256>>>(gamma, beta);
    bn_apply_kernel<<<(NB * NC * NL) / 2048, 256>>>(out);
}